// round 5
// baseline (speedup 1.0000x reference)
#include <cuda_runtime.h>
#include <cstdint>

// ---------------------------------------------------------------------------
// Problem constants: x shape (8, 2048, 1024) -> 16384 tokens x 1024 features.
// Expert 0: d=512 (sub dim 256). Expert 1: d=256 (sub dim 128).
// Output: opt (16384*1024 floats) followed by recon scalar.
// ---------------------------------------------------------------------------
#define TOK   16384
#define HDIM  1024
#define NTOT  (TOK * HDIM)   // 16777216

// Scratch (static device arrays: no allocation allowed in kernel_launch)
__device__ float g_hs[NTOT];        // 64 MB : hs = x + 0.002*noise
__device__ float g_h [TOK * 512];   // 32 MB : expert hidden (post tanh+dropout)
__device__ float g_t [TOK * 256];   // 16 MB : sub-network inner activation
__device__ float g_s [TOK * 512];   // 32 MB : sub-network output (tanh)

// ---------------------------------------------------------------------------
// Threefry2x32 (exact JAX PRNG core). Same code host + device.
// ---------------------------------------------------------------------------
__host__ __device__ __forceinline__ unsigned rotl32_(unsigned x, int r) {
    return (x << r) | (x >> (32 - r));
}

__host__ __device__ __forceinline__ void threefry2x32_(
    unsigned k0, unsigned k1, unsigned x0, unsigned x1,
    unsigned& o0, unsigned& o1)
{
    unsigned ks2 = k0 ^ k1 ^ 0x1BD11BDAu;
    unsigned ks[3] = {k0, k1, ks2};
    x0 += k0; x1 += k1;
    const int RA[4] = {13, 15, 26, 6};
    const int RB[4] = {17, 29, 16, 24};
#pragma unroll
    for (int r = 0; r < 5; ++r) {
        const int* R = (r & 1) ? RB : RA;
#pragma unroll
        for (int j = 0; j < 4; ++j) {
            x0 += x1;
            x1 = rotl32_(x1, R[j]);
            x1 ^= x0;
        }
        x0 += ks[(r + 1) % 3];
        x1 += ks[(r + 2) % 3] + (unsigned)(r + 1);
    }
    o0 = x0; o1 = x1;
}

// JAX bernoulli(key, 0.8, shape), PARTITIONABLE threefry (default since
// JAX 0.4.36): 32-bit random bits for flat element i are
//   (o0, o1) = threefry2x32(key, (0, i));  bits = o0 ^ o1
// uniform = bitcast((bits >> 9) | 0x3f800000) - 1;  keep iff u < 0.8.
__device__ __forceinline__ float dropout_val(
    float v, unsigned i, unsigned k0, unsigned k1)
{
    unsigned o0, o1;
    threefry2x32_(k0, k1, 0u, i, o0, o1);
    unsigned bits = o0 ^ o1;
    float u = __uint_as_float((bits >> 9) | 0x3f800000u) - 1.0f;
    return (u < 0.8f) ? (v * 1.25f) : 0.0f;
}

// ---------------------------------------------------------------------------
// Prep kernel: hs = x + 0.002*noise ; opt init = (route==2 ? hs : 0);
// zero the recon accumulator slot.
// ---------------------------------------------------------------------------
__global__ void prep_kernel(const float* __restrict__ x,
                            const float* __restrict__ noise,
                            const int*   __restrict__ route,
                            float* __restrict__ out,
                            float* __restrict__ recon)
{
    unsigned i4 = blockIdx.x * blockDim.x + threadIdx.x;
    unsigned base = i4 * 4u;
    if (base < (unsigned)NTOT) {
        float4 xv = *(const float4*)(x + base);
        float4 nv = *(const float4*)(noise + base);
        float4 h;
        h.x = xv.x + 0.002f * nv.x;
        h.y = xv.y + 0.002f * nv.y;
        h.z = xv.z + 0.002f * nv.z;
        h.w = xv.w + 0.002f * nv.w;
        *(float4*)(g_hs + base) = h;
        int s = (int)((base >> 10) & 2047u);   // token row % 2048
        float4 o = (route[s] == 2) ? h : make_float4(0.f, 0.f, 0.f, 0.f);
        *(float4*)(out + base) = o;
    }
    if (i4 == 0) *recon = 0.0f;
}

// ---------------------------------------------------------------------------
// Tiled fp32 GEMM: C[M,N] = A[M,K] @ B[K,N] (+bias), row-major everywhere.
// BM=BN=128, BK=8, 256 threads, 8x8 per-thread microtile.
// EPI 0: tanh -> dropout(key) -> store
// EPI 1: tanh -> store
// EPI 2: bias only; route-select write into d_out; block-reduced recon MSE
//        atomically accumulated into recon_out. A operand selected between
//        A0 (=h) and A1 (=s) by sub_choice[expert] (<2 -> s, ==2 -> h).
// branch_req >= 0: kernel no-ops unless sub_choice[expert] == branch_req.
// ---------------------------------------------------------------------------
#define BM 128
#define BN 128
#define BK 8
#define TM 8
#define TN 8

template <int EPI>
__global__ __launch_bounds__(256, 2)
void gemm_kernel(const float* __restrict__ A0, const float* __restrict__ A1,
                 const float* __restrict__ B,  const float* __restrict__ bias,
                 float* __restrict__ C,
                 int M, int N, int K,
                 const int* __restrict__ sub_choice, int expert, int branch_req,
                 unsigned key0, unsigned key1,
                 const float* __restrict__ hs, const int* __restrict__ route,
                 float* __restrict__ recon_out, float recon_scale)
{
    if (branch_req >= 0 && sub_choice[expert] != branch_req) return;

    const float* A = A0;
    if (EPI == 2) {
        A = (sub_choice[expert] < 2) ? A1 : A0;
    }

    __shared__ float As[BK][BM];
    __shared__ float Bs[BK][BN];
    __shared__ float red[256];

    const int tid  = threadIdx.x;
    const int brow = blockIdx.y * BM;
    const int bcol = blockIdx.x * BN;
    const int tx = tid & 15;    // 16 thread cols
    const int ty = tid >> 4;    // 16 thread rows

    const int a_row = tid >> 1;          // 0..127
    const int a_col = (tid & 1) * 4;     // 0 or 4
    const int b_row = tid >> 5;          // 0..7
    const int b_col = (tid & 31) * 4;    // 0..124

    const float* Ablk = A + (size_t)brow * K;

    float acc[TM][TN];
#pragma unroll
    for (int i = 0; i < TM; ++i)
#pragma unroll
        for (int j = 0; j < TN; ++j) acc[i][j] = 0.f;

    for (int k0 = 0; k0 < K; k0 += BK) {
        float4 av = *(const float4*)(Ablk + (size_t)a_row * K + k0 + a_col);
        float4 bv = *(const float4*)(B + (size_t)(k0 + b_row) * N + bcol + b_col);
        As[a_col + 0][a_row] = av.x;
        As[a_col + 1][a_row] = av.y;
        As[a_col + 2][a_row] = av.z;
        As[a_col + 3][a_row] = av.w;
        *(float4*)&Bs[b_row][b_col] = bv;
        __syncthreads();

#pragma unroll
        for (int kk = 0; kk < BK; ++kk) {
            float ar[TM], br[TN];
            *(float4*)&ar[0] = *(const float4*)&As[kk][ty * TM];
            *(float4*)&ar[4] = *(const float4*)&As[kk][ty * TM + 4];
            *(float4*)&br[0] = *(const float4*)&Bs[kk][tx * TN];
            *(float4*)&br[4] = *(const float4*)&Bs[kk][tx * TN + 4];
#pragma unroll
            for (int i = 0; i < TM; ++i)
#pragma unroll
                for (int j = 0; j < TN; ++j)
                    acc[i][j] += ar[i] * br[j];
        }
        __syncthreads();
    }

    float bsave[TN];
#pragma unroll
    for (int j = 0; j < TN; ++j) bsave[j] = bias[bcol + tx * TN + j];

    if (EPI == 0) {
#pragma unroll
        for (int i = 0; i < TM; ++i) {
            int r = brow + ty * TM + i;
#pragma unroll
            for (int j = 0; j < TN; ++j) {
                int c = bcol + tx * TN + j;
                float v = tanhf(acc[i][j] + bsave[j]);
                unsigned idx = (unsigned)r * (unsigned)N + (unsigned)c;
                C[idx] = dropout_val(v, idx, key0, key1);
            }
        }
    } else if (EPI == 1) {
#pragma unroll
        for (int i = 0; i < TM; ++i) {
            int r = brow + ty * TM + i;
#pragma unroll
            for (int j = 0; j < TN; ++j) {
                int c = bcol + tx * TN + j;
                C[(unsigned)r * (unsigned)N + (unsigned)c] =
                    tanhf(acc[i][j] + bsave[j]);
            }
        }
    } else {
        float lsum = 0.f;
#pragma unroll
        for (int i = 0; i < TM; ++i) {
            int r = brow + ty * TM + i;
            int rt = route[r & 2047];
#pragma unroll
            for (int j = 0; j < TN; ++j) {
                int c = bcol + tx * TN + j;
                float v = acc[i][j] + bsave[j];
                unsigned idx = (unsigned)r * (unsigned)N + (unsigned)c;
                float d = hs[idx] - v;
                lsum += d * d;
                if (rt == expert) C[idx] = v;
            }
        }
        red[tid] = lsum;
        __syncthreads();
#pragma unroll
        for (int s = 128; s > 0; s >>= 1) {
            if (tid < s) red[tid] += red[tid + s];
            __syncthreads();
        }
        if (tid == 0) atomicAdd(recon_out, red[0] * recon_scale);
    }
}

// ---------------------------------------------------------------------------
// Host side
// ---------------------------------------------------------------------------
extern "C" void kernel_launch(void* const* d_in, const int* in_sizes, int n_in,
                              void* d_out, int out_size)
{
    const float* x          = (const float*)d_in[0];
    const float* noise      = (const float*)d_in[1];
    const int*   route      = (const int*)  d_in[2];
    const int*   sub_choice = (const int*)  d_in[3];

    float* out   = (float*)d_out;
    float* recon = out + (out_size - 1);

    float *p_hs, *p_h, *p_t, *p_s;
    cudaGetSymbolAddress((void**)&p_hs, g_hs);
    cudaGetSymbolAddress((void**)&p_h,  g_h);
    cudaGetSymbolAddress((void**)&p_t,  g_t);
    cudaGetSymbolAddress((void**)&p_s,  g_s);

    // --- exact JAX key derivation, PARTITIONABLE (fold-like) split ---
    // dkey = key(42) = (0, 42).
    // split(dkey, 2): child e = threefry(dkey, (0, e)) -> (o0, o1) is the key.
    unsigned ek[2][2];
    threefry2x32_(0u, 42u, 0u, 0u, ek[0][0], ek[0][1]);
    threefry2x32_(0u, 42u, 0u, 1u, ek[1][0], ek[1][1]);

    // split(ek[e], 3): child j = threefry(ek[e], (0, j)).
    // j=0 -> expert-level dropout, j=1 -> s0 inner dropout, j=2 -> s1 inner.
    unsigned kk1[2][2], kk2[2][2], kk3[2][2];
    for (int e = 0; e < 2; ++e) {
        threefry2x32_(ek[e][0], ek[e][1], 0u, 0u, kk1[e][0], kk1[e][1]);
        threefry2x32_(ek[e][0], ek[e][1], 0u, 1u, kk2[e][0], kk2[e][1]);
        threefry2x32_(ek[e][0], ek[e][1], 0u, 2u, kk3[e][0], kk3[e][1]);
    }

    prep_kernel<<<NTOT / 4 / 256, 256>>>(x, noise, route, out, recon);

    const float recon_scale = 1.0f / (2.0f * (float)NTOT);
    const dim3 blk(256);

    for (int e = 0; e < 2; ++e) {
        int base = 4 + e * 12;
        const float* dw   = (const float*)d_in[base + 0];
        const float* db   = (const float*)d_in[base + 1];
        const float* s0dw = (const float*)d_in[base + 2];
        const float* s0db = (const float*)d_in[base + 3];
        const float* s0uw = (const float*)d_in[base + 4];
        const float* s0ub = (const float*)d_in[base + 5];
        const float* s1dw = (const float*)d_in[base + 6];
        const float* s1db = (const float*)d_in[base + 7];
        const float* s1uw = (const float*)d_in[base + 8];
        const float* s1ub = (const float*)d_in[base + 9];
        const float* uw   = (const float*)d_in[base + 10];
        const float* ub   = (const float*)d_in[base + 11];

        const int d  = (e == 0) ? 512 : 256;
        const int dh = d / 2;

        // GEMM1: hs @ dw -> tanh -> dropout(kk1) -> g_h
        gemm_kernel<0><<<dim3(d / BN, TOK / BM), blk>>>(
            p_hs, nullptr, dw, db, p_h,
            TOK, d, HDIM, sub_choice, e, -1,
            kk1[e][0], kk1[e][1],
            nullptr, nullptr, nullptr, 0.f);

        // s0 branch (runs only if sub_choice[e] == 0)
        gemm_kernel<0><<<dim3(dh / BN, TOK / BM), blk>>>(
            p_h, nullptr, s0dw, s0db, p_t,
            TOK, dh, d, sub_choice, e, 0,
            kk2[e][0], kk2[e][1],
            nullptr, nullptr, nullptr, 0.f);
        gemm_kernel<1><<<dim3(d / BN, TOK / BM), blk>>>(
            p_t, nullptr, s0uw, s0ub, p_s,
            TOK, d, dh, sub_choice, e, 0,
            0u, 0u, nullptr, nullptr, nullptr, 0.f);

        // s1 branch (runs only if sub_choice[e] == 1)
        gemm_kernel<0><<<dim3(dh / BN, TOK / BM), blk>>>(
            p_h, nullptr, s1dw, s1db, p_t,
            TOK, dh, d, sub_choice, e, 1,
            kk3[e][0], kk3[e][1],
            nullptr, nullptr, nullptr, 0.f);
        gemm_kernel<1><<<dim3(d / BN, TOK / BM), blk>>>(
            p_t, nullptr, s1uw, s1ub, p_s,
            TOK, d, dh, sub_choice, e, 1,
            0u, 0u, nullptr, nullptr, nullptr, 0.f);

        // GEMM3: (sub_choice<2 ? g_s : g_h) @ uw -> route-select into out,
        // recon MSE accumulated into recon slot.
        gemm_kernel<2><<<dim3(HDIM / BN, TOK / BM), blk>>>(
            p_h, p_s, uw, ub, out,
            TOK, HDIM, d, sub_choice, e, -1,
            0u, 0u, p_hs, route, recon, recon_scale);
    }
}

// round 8
// speedup vs baseline: 2.0591x; 2.0591x over previous
#include <cuda_runtime.h>
#include <cuda_bf16.h>
#include <cstdint>

// ---------------------------------------------------------------------------
// Problem: x (8,2048,1024) -> 16384 tokens x 1024. Expert0 d=512, Expert1 d=256.
// Output: opt (16384*1024 fp32) + recon scalar.
// Strategy: all GEMMs via mma.sync m16n8k16 bf16 (HMMA path; tcgen05 is
// rejected by this harness's compute_100 ptx target) with hi/lo split
// (3-MMA compensation) for fp32-grade accuracy.
// ---------------------------------------------------------------------------
#define TOK   16384
#define HDIM  1024
#define NTOT  (TOK * HDIM)

// ---------------- static scratch (no allocs allowed) -----------------------
__device__ float          g_hs[NTOT];
__device__ __nv_bfloat16  g_hs_hi[NTOT],      g_hs_lo[NTOT];
__device__ __nv_bfloat16  g_h_hi[TOK * 512],  g_h_lo[TOK * 512];
__device__ __nv_bfloat16  g_t_hi[TOK * 256],  g_t_lo[TOK * 256];
__device__ __nv_bfloat16  g_s_hi[TOK * 512],  g_s_lo[TOK * 512];
#define WTOT 2228224
__device__ __nv_bfloat16  g_w_hi[WTOT],       g_w_lo[WTOT];

// ---------------- threefry (exact JAX partitionable PRNG, verified R5) -----
__host__ __device__ __forceinline__ unsigned rotl32_(unsigned x, int r) {
    return (x << r) | (x >> (32 - r));
}
__host__ __device__ __forceinline__ void threefry2x32_(
    unsigned k0, unsigned k1, unsigned x0, unsigned x1,
    unsigned& o0, unsigned& o1)
{
    unsigned ks2 = k0 ^ k1 ^ 0x1BD11BDAu;
    unsigned ks[3] = {k0, k1, ks2};
    x0 += k0; x1 += k1;
    const int RA[4] = {13, 15, 26, 6};
    const int RB[4] = {17, 29, 16, 24};
#pragma unroll
    for (int r = 0; r < 5; ++r) {
        const int* R = (r & 1) ? RB : RA;
#pragma unroll
        for (int j = 0; j < 4; ++j) {
            x0 += x1; x1 = rotl32_(x1, R[j]); x1 ^= x0;
        }
        x0 += ks[(r + 1) % 3];
        x1 += ks[(r + 2) % 3] + (unsigned)(r + 1);
    }
    o0 = x0; o1 = x1;
}
__device__ __forceinline__ float dropout_val(
    float v, unsigned i, unsigned k0, unsigned k1)
{
    unsigned o0, o1;
    threefry2x32_(k0, k1, 0u, i, o0, o1);
    unsigned bits = o0 ^ o1;
    float u = __uint_as_float((bits >> 9) | 0x3f800000u) - 1.0f;
    return (u < 0.8f) ? (v * 1.25f) : 0.0f;
}

__device__ __forceinline__ void split_bf16(float a, __nv_bfloat16& hi, __nv_bfloat16& lo) {
    hi = __float2bfloat16(a);
    lo = __float2bfloat16(a - __bfloat162float(hi));
}

// ---------------- PTX helpers (all plain sm_80-era ISA) --------------------
__device__ __forceinline__ uint32_t smem_u32(const void* p) {
    uint32_t a;
    asm("{ .reg .u64 t; cvta.to.shared.u64 t, %1; cvt.u32.u64 %0, t; }"
        : "=r"(a) : "l"(p));
    return a;
}
__device__ __forceinline__ void cp16(uint32_t s, const void* g) {
    asm volatile("cp.async.cg.shared.global [%0], [%1], 16;"
                 :: "r"(s), "l"(g));
}
__device__ __forceinline__ void cp_commit() {
    asm volatile("cp.async.commit_group;" ::: "memory");
}
template <int N>
__device__ __forceinline__ void cp_wait() {
    asm volatile("cp.async.wait_group %0;" :: "n"(N) : "memory");
}
__device__ __forceinline__ void ldmx4(uint32_t a, uint32_t& r0, uint32_t& r1,
                                      uint32_t& r2, uint32_t& r3) {
    asm volatile("ldmatrix.sync.aligned.m8n8.x4.shared.b16 {%0,%1,%2,%3}, [%4];"
                 : "=r"(r0), "=r"(r1), "=r"(r2), "=r"(r3) : "r"(a));
}
__device__ __forceinline__ void mma16816(float* c, const uint32_t* a,
                                         const uint32_t* b) {
    asm volatile(
        "mma.sync.aligned.m16n8k16.row.col.f32.bf16.bf16.f32 "
        "{%0,%1,%2,%3}, {%4,%5,%6,%7}, {%8,%9}, {%0,%1,%2,%3};"
        : "+f"(c[0]), "+f"(c[1]), "+f"(c[2]), "+f"(c[3])
        : "r"(a[0]), "r"(a[1]), "r"(a[2]), "r"(a[3]), "r"(b[0]), "r"(b[1]));
}

// ---------------------------------------------------------------------------
// Prep: hs = x + 0.002*noise (fp32 + bf16 hi/lo); out init (route==2); recon=0
// ---------------------------------------------------------------------------
__global__ void prep_kernel(const float* __restrict__ x,
                            const float* __restrict__ noise,
                            const int*   __restrict__ route,
                            float* __restrict__ out,
                            float* __restrict__ recon)
{
    unsigned i4 = blockIdx.x * blockDim.x + threadIdx.x;
    unsigned base = i4 * 4u;
    if (base < (unsigned)NTOT) {
        float4 xv = *(const float4*)(x + base);
        float4 nv = *(const float4*)(noise + base);
        float4 h;
        h.x = xv.x + 0.002f * nv.x;
        h.y = xv.y + 0.002f * nv.y;
        h.z = xv.z + 0.002f * nv.z;
        h.w = xv.w + 0.002f * nv.w;
        *(float4*)(g_hs + base) = h;
        __nv_bfloat16 hi[4], lo[4];
        split_bf16(h.x, hi[0], lo[0]);
        split_bf16(h.y, hi[1], lo[1]);
        split_bf16(h.z, hi[2], lo[2]);
        split_bf16(h.w, hi[3], lo[3]);
        *(uint2*)(g_hs_hi + base) = *(uint2*)hi;
        *(uint2*)(g_hs_lo + base) = *(uint2*)lo;
        int s = (int)((base >> 10) & 2047u);
        float4 o = (route[s] == 2) ? h : make_float4(0.f, 0.f, 0.f, 0.f);
        *(float4*)(out + base) = o;
    }
    if (i4 == 0) *recon = 0.0f;
}

// W[K,N] fp32 -> Whi/Wlo[N,K] bf16 (transposed, K-major)
__global__ void wprep_kernel(const float* __restrict__ W,
                             __nv_bfloat16* __restrict__ hi,
                             __nv_bfloat16* __restrict__ lo,
                             int K, int N)
{
    int i = blockIdx.x * 256 + threadIdx.x;
    if (i >= K * N) return;
    int n = i / K, k = i % K;
    float v = W[(size_t)k * N + n];
    __nv_bfloat16 h, l;
    split_bf16(v, h, l);
    hi[i] = h; lo[i] = l;
}

// ---------------------------------------------------------------------------
// HMMA GEMM: C[16384, N] = A[M,K] @ W^T[N,K]^T (+bias), bf16 hi/lo 3-MMA.
// Tile 128x128, BK=32, 8 warps (4m x 2n), warp tile 32x64.
// 2-stage cp.async pipeline. SMEM rows padded to 40 elems (conflict-free
// for both cp.async stores and ldmatrix row patterns).
// ---------------------------------------------------------------------------
#define AS_STRIDE 40
#define TILE_B    (128 * AS_STRIDE * 2)        // 10240 bytes per tile
#define ST_AHI    0
#define ST_ALO    (TILE_B)
#define ST_BHI    (2 * TILE_B)
#define ST_BLO    (3 * TILE_B)
#define STAGE_B   (4 * TILE_B)                 // 40960
#define SMEM_BYTES (2 * STAGE_B)               // 81920

__device__ __forceinline__ void issue_stage(
    uint32_t sb, const __nv_bfloat16* Ahi, const __nv_bfloat16* Alo,
    const __nv_bfloat16* Bhi, const __nv_bfloat16* Blo,
    int brow, int bcol, int K, int k0, int tid)
{
#pragma unroll
    for (int it = 0; it < 2; ++it) {
        int idx = it * 256 + tid;          // 0..511
        int r = idx >> 2, c = idx & 3;
        uint32_t so = (uint32_t)((r * AS_STRIDE + c * 8) * 2);
        size_t ga = (size_t)(brow + r) * K + k0 + c * 8;
        size_t gb = (size_t)(bcol + r) * K + k0 + c * 8;
        cp16(sb + ST_AHI + so, Ahi + ga);
        cp16(sb + ST_ALO + so, Alo + ga);
        cp16(sb + ST_BHI + so, Bhi + gb);
        cp16(sb + ST_BLO + so, Blo + gb);
    }
    cp_commit();
}

template <int EPI>
__global__ void __launch_bounds__(256)
gemm_tc(const __nv_bfloat16* __restrict__ Ahi, const __nv_bfloat16* __restrict__ Alo,
        const __nv_bfloat16* __restrict__ A1hi, const __nv_bfloat16* __restrict__ A1lo,
        const __nv_bfloat16* __restrict__ Bhi, const __nv_bfloat16* __restrict__ Blo,
        const float* __restrict__ bias,
        __nv_bfloat16* __restrict__ Chi, __nv_bfloat16* __restrict__ Clo,
        float* __restrict__ outC,
        int N, int K,
        const int* __restrict__ sub_choice, int expert, int branch_req,
        unsigned key0, unsigned key1,
        const float* __restrict__ hs, const int* __restrict__ route,
        float* __restrict__ recon_out, float recon_scale)
{
    if (branch_req >= 0 && sub_choice[expert] != branch_req) return;
    if (EPI == 2 && sub_choice[expert] < 2) { Ahi = A1hi; Alo = A1lo; }

    extern __shared__ char smem[];
    uint32_t sbase = smem_u32(smem);

    const int tid = threadIdx.x;
    const int wid = tid >> 5, lane = tid & 31;
    const int wm = wid >> 1, wn = wid & 1;      // 4 x 2 warp grid
    const int brow = blockIdx.y * 128, bcol = blockIdx.x * 128;

    float acc[2][8][4];
#pragma unroll
    for (int mi = 0; mi < 2; ++mi)
#pragma unroll
        for (int nj = 0; nj < 8; ++nj)
#pragma unroll
            for (int c = 0; c < 4; ++c) acc[mi][nj][c] = 0.f;

    // ldmatrix source offsets (within a tile), in bytes
    const int a_row = wm * 32 + (lane & 15);            // + mi*16
    const int a_koff = (lane >> 4) * 8;
    const int b_row0 = wn * 64 + (lane & 7) + (lane >> 4) * 8;  // + g*16
    const int b_koff = ((lane >> 3) & 1) * 8;

    const int nch = K >> 5;
    issue_stage(sbase, Ahi, Alo, Bhi, Blo, brow, bcol, K, 0, tid);

    for (int kc = 0; kc < nch; ++kc) {
        if (kc + 1 < nch) {
            issue_stage(sbase + ((kc + 1) & 1) * STAGE_B,
                        Ahi, Alo, Bhi, Blo, brow, bcol, K, (kc + 1) << 5, tid);
            cp_wait<1>();
        } else {
            cp_wait<0>();
        }
        __syncthreads();

        uint32_t st = sbase + (kc & 1) * STAGE_B;
#pragma unroll
        for (int kk = 0; kk < 2; ++kk) {
            int k0s = kk * 16;
            uint32_t ah[2][4], al[2][4];
#pragma unroll
            for (int mi = 0; mi < 2; ++mi) {
                uint32_t ao = (uint32_t)(((a_row + mi * 16) * AS_STRIDE +
                                          k0s + a_koff) * 2);
                ldmx4(st + ST_AHI + ao, ah[mi][0], ah[mi][1], ah[mi][2], ah[mi][3]);
                ldmx4(st + ST_ALO + ao, al[mi][0], al[mi][1], al[mi][2], al[mi][3]);
            }
#pragma unroll
            for (int g = 0; g < 4; ++g) {
                uint32_t bo = (uint32_t)(((b_row0 + g * 16) * AS_STRIDE +
                                          k0s + b_koff) * 2);
                uint32_t bh[4], bl[4];
                ldmx4(st + ST_BHI + bo, bh[0], bh[1], bh[2], bh[3]);
                ldmx4(st + ST_BLO + bo, bl[0], bl[1], bl[2], bl[3]);
#pragma unroll
                for (int p = 0; p < 2; ++p) {
                    int nj = g * 2 + p;
                    uint32_t bfh[2] = {bh[p * 2], bh[p * 2 + 1]};
                    uint32_t bfl[2] = {bl[p * 2], bl[p * 2 + 1]};
#pragma unroll
                    for (int mi = 0; mi < 2; ++mi) {
                        mma16816(acc[mi][nj], ah[mi], bfh);
                        mma16816(acc[mi][nj], ah[mi], bfl);
                        mma16816(acc[mi][nj], al[mi], bfh);
                    }
                }
            }
        }
        __syncthreads();
    }

    // ----------------- epilogue (direct from fragments) -----------------
    const int lane4 = lane >> 2;          // 0..7
    const int lanec = (lane & 3) * 2;
    float lsum = 0.f;

#pragma unroll
    for (int mi = 0; mi < 2; ++mi) {
        int r0g = brow + wm * 32 + mi * 16 + lane4;
        int r1g = r0g + 8;
        int rt0 = 0, rt1 = 0;
        if (EPI == 2) {
            rt0 = route[r0g & 2047];
            rt1 = route[r1g & 2047];
        }
#pragma unroll
        for (int nj = 0; nj < 8; ++nj) {
            int col = bcol + wn * 64 + nj * 8 + lanec;
            float b0 = bias[col], b1 = bias[col + 1];
            float v00 = acc[mi][nj][0] + b0, v01 = acc[mi][nj][1] + b1;
            float v10 = acc[mi][nj][2] + b0, v11 = acc[mi][nj][3] + b1;
            unsigned i0 = (unsigned)r0g * (unsigned)N + (unsigned)col;
            unsigned i1 = (unsigned)r1g * (unsigned)N + (unsigned)col;

            if (EPI == 0 || EPI == 1) {
                v00 = tanhf(v00); v01 = tanhf(v01);
                v10 = tanhf(v10); v11 = tanhf(v11);
                if (EPI == 0) {
                    v00 = dropout_val(v00, i0, key0, key1);
                    v01 = dropout_val(v01, i0 + 1, key0, key1);
                    v10 = dropout_val(v10, i1, key0, key1);
                    v11 = dropout_val(v11, i1 + 1, key0, key1);
                }
                __nv_bfloat16 h0, l0, h1, l1;
                __nv_bfloat162 ph, pl;
                split_bf16(v00, h0, l0); split_bf16(v01, h1, l1);
                ph.x = h0; ph.y = h1; pl.x = l0; pl.y = l1;
                *(__nv_bfloat162*)(Chi + i0) = ph;
                *(__nv_bfloat162*)(Clo + i0) = pl;
                split_bf16(v10, h0, l0); split_bf16(v11, h1, l1);
                ph.x = h0; ph.y = h1; pl.x = l0; pl.y = l1;
                *(__nv_bfloat162*)(Chi + i1) = ph;
                *(__nv_bfloat162*)(Clo + i1) = pl;
            } else {
                float d;
                d = hs[i0] - v00;     lsum += d * d;
                d = hs[i0 + 1] - v01; lsum += d * d;
                d = hs[i1] - v10;     lsum += d * d;
                d = hs[i1 + 1] - v11; lsum += d * d;
                if (rt0 == expert) {
                    outC[i0] = v00; outC[i0 + 1] = v01;
                }
                if (rt1 == expert) {
                    outC[i1] = v10; outC[i1 + 1] = v11;
                }
            }
        }
    }

    if (EPI == 2) {
#pragma unroll
        for (int s = 16; s > 0; s >>= 1)
            lsum += __shfl_xor_sync(0xFFFFFFFFu, lsum, s);
        if (lane == 0) atomicAdd(recon_out, lsum * recon_scale);
    }
}

// ---------------------------------------------------------------------------
// Host side
// ---------------------------------------------------------------------------
extern "C" void kernel_launch(void* const* d_in, const int* in_sizes, int n_in,
                              void* d_out, int out_size)
{
    const float* x          = (const float*)d_in[0];
    const float* noise      = (const float*)d_in[1];
    const int*   route      = (const int*)  d_in[2];
    const int*   sub_choice = (const int*)  d_in[3];

    float* out   = (float*)d_out;
    float* recon = out + (out_size - 1);

    float* p_hs;
    __nv_bfloat16 *p_hs_hi, *p_hs_lo, *p_h_hi, *p_h_lo, *p_t_hi, *p_t_lo,
                  *p_s_hi, *p_s_lo, *p_w_hi, *p_w_lo;
    cudaGetSymbolAddress((void**)&p_hs,    g_hs);
    cudaGetSymbolAddress((void**)&p_hs_hi, g_hs_hi);
    cudaGetSymbolAddress((void**)&p_hs_lo, g_hs_lo);
    cudaGetSymbolAddress((void**)&p_h_hi,  g_h_hi);
    cudaGetSymbolAddress((void**)&p_h_lo,  g_h_lo);
    cudaGetSymbolAddress((void**)&p_t_hi,  g_t_hi);
    cudaGetSymbolAddress((void**)&p_t_lo,  g_t_lo);
    cudaGetSymbolAddress((void**)&p_s_hi,  g_s_hi);
    cudaGetSymbolAddress((void**)&p_s_lo,  g_s_lo);
    cudaGetSymbolAddress((void**)&p_w_hi,  g_w_hi);
    cudaGetSymbolAddress((void**)&p_w_lo,  g_w_lo);

    cudaFuncSetAttribute(gemm_tc<0>, cudaFuncAttributeMaxDynamicSharedMemorySize, SMEM_BYTES);
    cudaFuncSetAttribute(gemm_tc<1>, cudaFuncAttributeMaxDynamicSharedMemorySize, SMEM_BYTES);
    cudaFuncSetAttribute(gemm_tc<2>, cudaFuncAttributeMaxDynamicSharedMemorySize, SMEM_BYTES);

    // --- exact JAX partitionable key derivation (verified R5) ---
    unsigned ek[2][2];
    threefry2x32_(0u, 42u, 0u, 0u, ek[0][0], ek[0][1]);
    threefry2x32_(0u, 42u, 0u, 1u, ek[1][0], ek[1][1]);
    unsigned kk1[2][2], kk2[2][2], kk3[2][2];
    for (int e = 0; e < 2; ++e) {
        threefry2x32_(ek[e][0], ek[e][1], 0u, 0u, kk1[e][0], kk1[e][1]);
        threefry2x32_(ek[e][0], ek[e][1], 0u, 1u, kk2[e][0], kk2[e][1]);
        threefry2x32_(ek[e][0], ek[e][1], 0u, 2u, kk3[e][0], kk3[e][1]);
    }

    prep_kernel<<<NTOT / 4 / 256, 256>>>(x, noise, route, out, recon);

    // --- weight prep: transpose + bf16 split ---
    long woff[2][6];
    {
        long off = 0;
        for (int e = 0; e < 2; ++e) {
            int d = (e == 0) ? 512 : 256, dh = d / 2;
            int Ks[6] = {HDIM, d, dh, d, dh, d};
            int Ns[6] = {d, dh, d, dh, d, HDIM};
            for (int wi = 0; wi < 6; ++wi) {
                woff[e][wi] = off;
                off += (long)Ks[wi] * Ns[wi];
            }
        }
    }
    for (int e = 0; e < 2; ++e) {
        int base = 4 + e * 12;
        int d = (e == 0) ? 512 : 256, dh = d / 2;
        const float* srcs[6] = {
            (const float*)d_in[base + 0],   // dw   [1024, d]
            (const float*)d_in[base + 2],   // s0dw [d, dh]
            (const float*)d_in[base + 4],   // s0uw [dh, d]
            (const float*)d_in[base + 6],   // s1dw [d, dh]
            (const float*)d_in[base + 8],   // s1uw [dh, d]
            (const float*)d_in[base + 10],  // uw   [d, 1024]
        };
        int Ks[6] = {HDIM, d, dh, d, dh, d};
        int Ns[6] = {d, dh, d, dh, d, HDIM};
        for (int wi = 0; wi < 6; ++wi) {
            int tot = Ks[wi] * Ns[wi];
            wprep_kernel<<<(tot + 255) / 256, 256>>>(
                srcs[wi], p_w_hi + woff[e][wi], p_w_lo + woff[e][wi],
                Ks[wi], Ns[wi]);
        }
    }

    const float recon_scale = 1.0f / (2.0f * (float)NTOT);

    for (int e = 0; e < 2; ++e) {
        int base = 4 + e * 12;
        const float* db   = (const float*)d_in[base + 1];
        const float* s0db = (const float*)d_in[base + 3];
        const float* s0ub = (const float*)d_in[base + 5];
        const float* s1db = (const float*)d_in[base + 7];
        const float* s1ub = (const float*)d_in[base + 9];
        const float* ub   = (const float*)d_in[base + 11];
        int d = (e == 0) ? 512 : 256, dh = d / 2;

        // GEMM1: hs @ dw -> tanh -> dropout -> h (bf16 hi/lo)
        gemm_tc<0><<<dim3(d / 128, TOK / 128), 256, SMEM_BYTES>>>(
            p_hs_hi, p_hs_lo, nullptr, nullptr,
            p_w_hi + woff[e][0], p_w_lo + woff[e][0], db,
            p_h_hi, p_h_lo, nullptr,
            d, HDIM, sub_choice, e, -1, kk1[e][0], kk1[e][1],
            nullptr, nullptr, nullptr, 0.f);

        // s0 branch
        gemm_tc<0><<<dim3(dh / 128, TOK / 128), 256, SMEM_BYTES>>>(
            p_h_hi, p_h_lo, nullptr, nullptr,
            p_w_hi + woff[e][1], p_w_lo + woff[e][1], s0db,
            p_t_hi, p_t_lo, nullptr,
            dh, d, sub_choice, e, 0, kk2[e][0], kk2[e][1],
            nullptr, nullptr, nullptr, 0.f);
        gemm_tc<1><<<dim3(d / 128, TOK / 128), 256, SMEM_BYTES>>>(
            p_t_hi, p_t_lo, nullptr, nullptr,
            p_w_hi + woff[e][2], p_w_lo + woff[e][2], s0ub,
            p_s_hi, p_s_lo, nullptr,
            d, dh, sub_choice, e, 0, 0u, 0u,
            nullptr, nullptr, nullptr, 0.f);

        // s1 branch
        gemm_tc<0><<<dim3(dh / 128, TOK / 128), 256, SMEM_BYTES>>>(
            p_h_hi, p_h_lo, nullptr, nullptr,
            p_w_hi + woff[e][3], p_w_lo + woff[e][3], s1db,
            p_t_hi, p_t_lo, nullptr,
            dh, d, sub_choice, e, 1, kk3[e][0], kk3[e][1],
            nullptr, nullptr, nullptr, 0.f);
        gemm_tc<1><<<dim3(d / 128, TOK / 128), 256, SMEM_BYTES>>>(
            p_t_hi, p_t_lo, nullptr, nullptr,
            p_w_hi + woff[e][4], p_w_lo + woff[e][4], s1ub,
            p_s_hi, p_s_lo, nullptr,
            d, dh, sub_choice, e, 1, 0u, 0u,
            nullptr, nullptr, nullptr, 0.f);

        // GEMM3: (choice<2 ? s : h) @ uw -> route-select out + recon
        gemm_tc<2><<<dim3(HDIM / 128, TOK / 128), 256, SMEM_BYTES>>>(
            p_h_hi, p_h_lo, p_s_hi, p_s_lo,
            p_w_hi + woff[e][5], p_w_lo + woff[e][5], ub,
            nullptr, nullptr, out,
            HDIM, d, sub_choice, e, -1, 0u, 0u,
            p_hs, route, recon, recon_scale);
    }
}